// round 1
// baseline (speedup 1.0000x reference)
#include <cuda_runtime.h>
#include <cuda_bf16.h>

#define IN_DIM 128
#define HID 32
#define NEG_SLOPE 0.2f
#define MAXN 100000
#define MAXE 1600000

// Scratch (device globals — no allocation allowed)
__device__ float g_h[MAXN * HID];      // current layer node features h = x@W
__device__ float g_el[MAXN];
__device__ float g_er[MAXN];
__device__ float g_denom[MAXN];
__device__ float g_ex[MAXE];
__device__ float g_agg[MAXN * HID];    // layer-1 aggregation result

// ---------------------------------------------------------------------------
// Zero denom + agg (layer 1 prologue)
__global__ void k_zero1(int N) {
    int i = blockIdx.x * blockDim.x + threadIdx.x;
    if (i < N * HID) g_agg[i] = 0.f;
    if (i < N) g_denom[i] = 0.f;
}

// Zero denom + init out rows to bias (layer 2 prologue)
__global__ void k_zero2(float* __restrict__ out, const float* __restrict__ b2, int N) {
    int i = blockIdx.x * blockDim.x + threadIdx.x;
    if (i < N * HID) out[i] = b2[i & (HID - 1)];
    if (i < N) g_denom[i] = 0.f;
}

// ---------------------------------------------------------------------------
// Layer-1 GEMM: h = x @ W1 ; el = h@al ; er = h@ar
// One warp per node, lane = output dim.
__global__ void k_gemm1(const float* __restrict__ x, const float* __restrict__ W,
                        const float* __restrict__ al, const float* __restrict__ ar,
                        int N) {
    __shared__ float Ws[IN_DIM * HID];
    for (int i = threadIdx.x; i < IN_DIM * HID; i += blockDim.x) Ws[i] = W[i];
    __syncthreads();

    int node = (blockIdx.x * blockDim.x + threadIdx.x) >> 5;
    int lane = threadIdx.x & 31;
    if (node >= N) return;

    const float4* xr = (const float4*)(x + (size_t)node * IN_DIM);
    float acc = 0.f;
#pragma unroll
    for (int k4 = 0; k4 < IN_DIM / 4; k4++) {
        float4 xv = xr[k4];  // uniform across warp (broadcast)
        acc += xv.x * Ws[(k4 * 4 + 0) * HID + lane];
        acc += xv.y * Ws[(k4 * 4 + 1) * HID + lane];
        acc += xv.z * Ws[(k4 * 4 + 2) * HID + lane];
        acc += xv.w * Ws[(k4 * 4 + 3) * HID + lane];
    }
    g_h[node * HID + lane] = acc;

    float vl = acc * al[lane];
    float vr = acc * ar[lane];
#pragma unroll
    for (int o = 16; o; o >>= 1) {
        vl += __shfl_xor_sync(0xffffffffu, vl, o);
        vr += __shfl_xor_sync(0xffffffffu, vr, o);
    }
    if (lane == 0) { g_el[node] = vl; g_er[node] = vr; }
}

// ---------------------------------------------------------------------------
// Layer-2 GEMM: hmid = elu(agg + b1); h = hmid @ W2; el, er
// One warp per node; lane k holds hmid_k, shuffled to all lanes.
__global__ void k_gemm2(const float* __restrict__ W2, const float* __restrict__ b1,
                        const float* __restrict__ al, const float* __restrict__ ar,
                        int N) {
    __shared__ float Ws[HID * HID];
    for (int i = threadIdx.x; i < HID * HID; i += blockDim.x) Ws[i] = W2[i];
    __syncthreads();

    int node = (blockIdx.x * blockDim.x + threadIdx.x) >> 5;
    int lane = threadIdx.x & 31;
    if (node >= N) return;

    float v = g_agg[node * HID + lane] + b1[lane];
    v = (v > 0.f) ? v : expm1f(v);  // ELU(alpha=1)

    float acc = 0.f;
#pragma unroll
    for (int k = 0; k < HID; k++) {
        acc += __shfl_sync(0xffffffffu, v, k) * Ws[k * HID + lane];
    }
    g_h[node * HID + lane] = acc;  // overwrite (layer-1 h no longer needed)

    float vl = acc * al[lane];
    float vr = acc * ar[lane];
#pragma unroll
    for (int o = 16; o; o >>= 1) {
        vl += __shfl_xor_sync(0xffffffffu, vl, o);
        vr += __shfl_xor_sync(0xffffffffu, vr, o);
    }
    if (lane == 0) { g_el[node] = vl; g_er[node] = vr; }
}

// ---------------------------------------------------------------------------
// Edge pass 1: ex = exp(leakyrelu(el[src]+er[dst])); denom[dst] += ex
// (segment-max dropped: alpha is scale-invariant and |e| is small)
__global__ void k_edge_denom(const int* __restrict__ src, const int* __restrict__ dst,
                             int E) {
    int e = blockIdx.x * blockDim.x + threadIdx.x;
    if (e >= E) return;
    int s = src[e], d = dst[e];
    float t = g_el[s] + g_er[d];
    float lr = (t > 0.f) ? t : NEG_SLOPE * t;
    float ex = expf(lr);
    g_ex[e] = ex;
    atomicAdd(&g_denom[d], ex);
}

// ---------------------------------------------------------------------------
// Edge pass 2: out[dst] += (ex/denom[dst]) * h[src]   via red.global.add.v4.f32
__global__ void k_edge_agg(const int* __restrict__ src, const int* __restrict__ dst,
                           float* __restrict__ out, int E) {
    int e = blockIdx.x * blockDim.x + threadIdx.x;
    if (e >= E) return;
    int s = src[e], d = dst[e];
    float alpha = g_ex[e] / g_denom[d];
    const float4* hs = (const float4*)(g_h + (size_t)s * HID);
    float4* op = (float4*)(out + (size_t)d * HID);
#pragma unroll
    for (int i = 0; i < HID / 4; i++) {
        float4 hv = hs[i];
        asm volatile(
            "red.global.add.v4.f32 [%0], {%1, %2, %3, %4};"
            :: "l"(op + i),
               "f"(alpha * hv.x), "f"(alpha * hv.y),
               "f"(alpha * hv.z), "f"(alpha * hv.w)
            : "memory");
    }
}

// ---------------------------------------------------------------------------
extern "C" void kernel_launch(void* const* d_in, const int* in_sizes, int n_in,
                              void* d_out, int out_size) {
    const float* features = (const float*)d_in[0];
    const int*   src      = (const int*)d_in[1];
    const int*   dst      = (const int*)d_in[2];
    const float* W1  = (const float*)d_in[3];
    const float* al1 = (const float*)d_in[4];
    const float* ar1 = (const float*)d_in[5];
    const float* b1  = (const float*)d_in[6];
    const float* W2  = (const float*)d_in[7];
    const float* al2 = (const float*)d_in[8];
    const float* ar2 = (const float*)d_in[9];
    const float* b2  = (const float*)d_in[10];
    float* out = (float*)d_out;

    int N = in_sizes[0] / IN_DIM;
    int E = in_sizes[1];

    const int TB = 256;
    int gridNodeWarps = (N * 32 + TB - 1) / TB;  // 1 warp/node
    int gridNH        = (N * HID + TB - 1) / TB;
    int gridE         = (E + TB - 1) / TB;

    // ---- Layer 1 ----
    k_zero1<<<gridNH, TB>>>(N);
    k_gemm1<<<gridNodeWarps, TB>>>(features, W1, al1, ar1, N);
    k_edge_denom<<<gridE, TB>>>(src, dst, E);
    // aggregate into g_agg
    {
        float* aggp = nullptr;
        cudaGetSymbolAddress((void**)&aggp, g_agg);
        k_edge_agg<<<gridE, TB>>>(src, dst, aggp, E);
    }

    // ---- Layer 2 ----
    k_zero2<<<gridNH, TB>>>(out, b2, N);
    k_gemm2<<<gridNodeWarps, TB>>>(W2, b1, al2, ar2, N);
    k_edge_denom<<<gridE, TB>>>(src, dst, E);
    k_edge_agg<<<gridE, TB>>>(src, dst, out, E);
}